// round 1
// baseline (speedup 1.0000x reference)
#include <cuda_runtime.h>
#include <cuda_bf16.h>
#include <cstddef>

// ---------------- problem constants ----------------
#define BATCH   8
#define EMEM    2
#define BE      16          // BATCH*EMEM
#define NTOK    512
#define ROWS    (BE*NTOK)   // 8192
#define DIM     768
#define NHEADS  12
#define HDIM    64
#define LAYERS  8
#define DMLP    3072
#define QKVD    2304
#define VIEWS   2

// ---------------- scratch (static device globals; no allocation) ----------------
__device__ float g_x[ROWS*DIM];          // residual stream
__device__ float g_h[ROWS*DIM];          // LN output / attention output
__device__ float g_qkv[ROWS*QKVD];       // qkv activations
__device__ float g_mlp[ROWS*DMLP];       // mlp hidden
__device__ float g_s[(size_t)BE*NHEADS*NTOK*NTOK]; // attention scores (201 MB)
__device__ int   g_vismode;              // 0=uint8, 1=int32, 2=float32

// ---------------- helpers ----------------
__device__ __forceinline__ float gelu_f(float x) {
    // jax.nn.gelu default (approximate=True): tanh formulation
    float x3 = x*x*x;
    return 0.5f*x*(1.f + tanhf(0.79788456080286535588f*(x + 0.044715f*x3)));
}

// ---------------- probe dtype of `visible` ----------------
__global__ void probe_visible(const unsigned char* __restrict__ vis) {
    if (threadIdx.x == 0 && blockIdx.x == 0) {
        int nz1 = 0, nz3f = 0;
        for (int i = 0; i < 4096; i++) {
            int m = i & 3;
            if (m == 1 && vis[i]) nz1++;
            if (m == 3 && vis[i]) nz3f++;
        }
        // uint8 bool: random nonzero bytes at all offsets
        // int32  0/1: bytes at offsets 1,2,3 all zero
        // float32 1.0f: byte3 = 0x3F (nonzero), byte1 = 0
        if (nz1 != 0)       g_vismode = 0;
        else if (nz3f != 0) g_vismode = 2;
        else                g_vismode = 1;
    }
}

// ---------------- patch embed + mask + pos + noise bias ----------------
__global__ void embed_kernel(const float* __restrict__ fields,
                             const unsigned char* __restrict__ visible,
                             const float* __restrict__ W_in,
                             const float* __restrict__ mask_emb,
                             const float* __restrict__ pos_emb,
                             const float* __restrict__ noise_b,
                             float* __restrict__ xout)
{
    int row = blockIdx.x;            // 0..8191 : be*512 + n
    int be  = row >> 9;
    int n   = row & 511;
    int b   = be >> 1;               // be / EMEM
    int h   = n >> 5;                // n / 32
    int w   = n & 31;

    int vi = b*NTOK + n;
    bool vis;
    int mode = g_vismode;
    if (mode == 1)      vis = ((const int*)visible)[vi] != 0;
    else if (mode == 2) vis = ((const float*)visible)[vi] != 0.f;
    else                vis = visible[vi] != 0;

    __shared__ float fv[32];
    if (threadIdx.x < 32) {
        int v = threadIdx.x >> 4;
        int p = (threadIdx.x >> 2) & 3;
        int q = threadIdx.x & 3;
        fv[threadIdx.x] = fields[((size_t)(b*VIEWS + v)*64 + (h*4+p))*128 + (w*4+q)];
    }
    __syncthreads();

    for (int d = threadIdx.x; d < DIM; d += blockDim.x) {
        float acc;
        if (vis) {
            acc = 0.f;
            #pragma unroll
            for (int t = 0; t < 32; t++) acc += fv[t] * W_in[t*DIM + d];
        } else {
            acc = mask_emb[d];
        }
        xout[(size_t)row*DIM + d] = acc + pos_emb[n*DIM + d] + noise_b[d];
    }
}

// ---------------- generic 128x128x8 SGEMM, fused bias/gelu/residual ----------------
// flags: bit0 = gelu, bit1 = accumulate into C
__global__ void __launch_bounds__(256) sgemm128(
    const float* __restrict__ A, int lda,
    const float* __restrict__ B, int ldb,
    float* __restrict__ C, int ldc,
    int K, const float* __restrict__ bias, int flags)
{
    __shared__ float As[8][132];
    __shared__ float Bs[8][128];
    const int tid = threadIdx.x;
    const int tr = tid >> 4, tc = tid & 15;
    const int row0 = blockIdx.y * 128, col0 = blockIdx.x * 128;

    float acc[8][8];
    #pragma unroll
    for (int i = 0; i < 8; i++)
        #pragma unroll
        for (int j = 0; j < 8; j++) acc[i][j] = 0.f;

    for (int k0 = 0; k0 < K; k0 += 8) {
        #pragma unroll
        for (int i = 0; i < 4; i++) {
            int e = tid + i*256;
            int m = e >> 3, k = e & 7;
            As[k][m] = A[(size_t)(row0+m)*lda + k0 + k];
            int k2 = e >> 7, n = e & 127;
            Bs[k2][n] = B[(size_t)(k0+k2)*ldb + col0 + n];
        }
        __syncthreads();
        #pragma unroll
        for (int k = 0; k < 8; k++) {
            float a[8], b[8];
            #pragma unroll
            for (int i = 0; i < 8; i++) a[i] = As[k][tr*8 + i];
            #pragma unroll
            for (int j = 0; j < 8; j++) b[j] = Bs[k][tc*8 + j];
            #pragma unroll
            for (int i = 0; i < 8; i++)
                #pragma unroll
                for (int j = 0; j < 8; j++) acc[i][j] += a[i]*b[j];
        }
        __syncthreads();
    }

    #pragma unroll
    for (int i = 0; i < 8; i++) {
        int m = row0 + tr*8 + i;
        #pragma unroll
        for (int j = 0; j < 8; j++) {
            int n = col0 + tc*8 + j;
            float v = acc[i][j];
            if (bias) v += bias[n];
            if (flags & 1) v = gelu_f(v);
            size_t ci = (size_t)m*ldc + n;
            if (flags & 2) v += C[ci];
            C[ci] = v;
        }
    }
}

// ---------------- attention: S = scale * Q K^T (batched over be*nh) ----------------
__global__ void __launch_bounds__(256) attn_qk(const float* __restrict__ qkv,
                                               float* __restrict__ S)
{
    int bh = blockIdx.z;                 // 0..191
    int be = bh / NHEADS, nh = bh % NHEADS;
    const float* Q  = qkv + (size_t)be*NTOK*QKVD + nh*HDIM;
    const float* Kp = Q + DIM;

    __shared__ float Qs[64][65];
    __shared__ float Ks[64][65];
    int tid = threadIdx.x;
    int qt = blockIdx.y * 64, kt = blockIdx.x * 64;

    #pragma unroll
    for (int i = 0; i < 16; i++) {
        int e = tid + i*256;
        int r = e >> 6, c = e & 63;
        Qs[r][c] = Q [(size_t)(qt+r)*QKVD + c];
        Ks[r][c] = Kp[(size_t)(kt+r)*QKVD + c];
    }
    __syncthreads();

    int tr = tid >> 4, tc = tid & 15;
    float acc[4][4] = {};
    #pragma unroll
    for (int k = 0; k < 64; k++) {
        float a[4], b[4];
        #pragma unroll
        for (int i = 0; i < 4; i++) a[i] = Qs[tr*4+i][k];
        #pragma unroll
        for (int j = 0; j < 4; j++) b[j] = Ks[tc*4+j][k];
        #pragma unroll
        for (int i = 0; i < 4; i++)
            #pragma unroll
            for (int j = 0; j < 4; j++) acc[i][j] += a[i]*b[j];
    }

    float* Sb = S + (size_t)bh*NTOK*NTOK;
    const float scale = 0.125f; // 1/sqrt(64)
    #pragma unroll
    for (int i = 0; i < 4; i++)
        #pragma unroll
        for (int j = 0; j < 4; j++)
            Sb[(size_t)(qt + tr*4 + i)*NTOK + kt + tc*4 + j] = acc[i][j]*scale;
}

// ---------------- softmax over last dim (rows of 512) ----------------
__global__ void softmax512(float* __restrict__ S)
{
    size_t row = blockIdx.x;
    float* p = S + row*512;
    int tid = threadIdx.x;
    float a = p[tid], b = p[tid+256];
    __shared__ float red[256];
    red[tid] = fmaxf(a, b);
    __syncthreads();
    for (int s = 128; s > 0; s >>= 1) {
        if (tid < s) red[tid] = fmaxf(red[tid], red[tid+s]);
        __syncthreads();
    }
    float m = red[0];
    __syncthreads();
    float e0 = __expf(a - m), e1 = __expf(b - m);
    red[tid] = e0 + e1;
    __syncthreads();
    for (int s = 128; s > 0; s >>= 1) {
        if (tid < s) red[tid] += red[tid+s];
        __syncthreads();
    }
    float inv = 1.f / red[0];
    p[tid]     = e0 * inv;
    p[tid+256] = e1 * inv;
}

// ---------------- attention: O = P @ V ----------------
__global__ void __launch_bounds__(256) attn_pv(const float* __restrict__ S,
                                               const float* __restrict__ qkv,
                                               float* __restrict__ H)
{
    int bh = blockIdx.y;                 // 0..191
    int qt = blockIdx.x * 64;            // 8 query tiles
    int be = bh / NHEADS, nh = bh % NHEADS;
    const float* P  = S + (size_t)bh*NTOK*NTOK;
    const float* Vv = qkv + (size_t)be*NTOK*QKVD + 2*DIM + nh*HDIM;

    __shared__ float Ps[64][33];
    __shared__ float Vs[32][65];
    int tid = threadIdx.x;
    int tr = tid >> 4, tc = tid & 15;
    float acc[4][4] = {};

    for (int k0 = 0; k0 < NTOK; k0 += 32) {
        #pragma unroll
        for (int i = 0; i < 8; i++) {
            int e = tid + i*256;
            int r = e >> 5, c = e & 31;
            Ps[r][c] = P[(size_t)(qt+r)*NTOK + k0 + c];
            int r2 = e >> 6, c2 = e & 63;
            Vs[r2][c2] = Vv[(size_t)(k0+r2)*QKVD + c2];
        }
        __syncthreads();
        #pragma unroll
        for (int k = 0; k < 32; k++) {
            float a[4], b[4];
            #pragma unroll
            for (int i = 0; i < 4; i++) a[i] = Ps[tr*4+i][k];
            #pragma unroll
            for (int j = 0; j < 4; j++) b[j] = Vs[k][tc*4+j];
            #pragma unroll
            for (int i = 0; i < 4; i++)
                #pragma unroll
                for (int j = 0; j < 4; j++) acc[i][j] += a[i]*b[j];
        }
        __syncthreads();
    }

    #pragma unroll
    for (int i = 0; i < 4; i++) {
        int m = qt + tr*4 + i;
        #pragma unroll
        for (int j = 0; j < 4; j++) {
            H[(size_t)(be*NTOK + m)*DIM + nh*HDIM + tc*4 + j] = acc[i][j];
        }
    }
}

// ---------------- layernorm (one block per row) ----------------
__global__ void ln_kernel(const float* __restrict__ x,
                          const float* __restrict__ s,
                          const float* __restrict__ b,
                          float* __restrict__ h)
{
    int row = blockIdx.x;
    const float* xr = x + (size_t)row*DIM;
    int tid = threadIdx.x;
    float v0 = xr[tid], v1 = xr[tid+256], v2 = xr[tid+512];
    __shared__ float red[256];
    red[tid] = v0 + v1 + v2;
    __syncthreads();
    for (int st = 128; st > 0; st >>= 1) {
        if (tid < st) red[tid] += red[tid+st];
        __syncthreads();
    }
    float mu = red[0] * (1.f/768.f);
    __syncthreads();
    float d0 = v0-mu, d1 = v1-mu, d2 = v2-mu;
    red[tid] = d0*d0 + d1*d1 + d2*d2;
    __syncthreads();
    for (int st = 128; st > 0; st >>= 1) {
        if (tid < st) red[tid] += red[tid+st];
        __syncthreads();
    }
    float rstd = rsqrtf(red[0]*(1.f/768.f) + 1e-5f);
    float* hr = h + (size_t)row*DIM;
    hr[tid]     = d0*rstd*s[tid]     + b[tid];
    hr[tid+256] = d1*rstd*s[tid+256] + b[tid+256];
    hr[tid+512] = d2*rstd*s[tid+512] + b[tid+512];
}

// ---------------- unpatchify + output transpose ----------------
__global__ void out_kernel(const float* __restrict__ x,
                           const float* __restrict__ W_out,
                           float* __restrict__ out)
{
    int idx = blockIdx.x*blockDim.x + threadIdx.x;   // 0..262143
    int e  = idx & 1;
    int Wc = (idx >> 1) & 127;
    int Hc = (idx >> 8) & 63;
    int v  = (idx >> 14) & 1;
    int b  = idx >> 15;
    int h = Hc >> 2, p = Hc & 3, w = Wc >> 2, q = Wc & 3;
    int row = (b*EMEM + e)*NTOK + h*32 + w;
    const float* xr = x + (size_t)row*DIM;
    const float* wr = W_out + ((size_t)v*DIM)*16 + p*4 + q;
    float acc = 0.f;
    #pragma unroll 4
    for (int d = 0; d < DIM; d++) acc += xr[d] * wr[(size_t)d*16];
    out[idx] = acc;
}

// ---------------- driver ----------------
extern "C" void kernel_launch(void* const* d_in, const int* in_sizes, int n_in,
                              void* d_out, int out_size)
{
    const float* fields   = (const float*)d_in[0];
    const unsigned char* visible = (const unsigned char*)d_in[1];
    const float* z        = (const float*)d_in[2];
    const float* W_in     = (const float*)d_in[3];
    const float* W_out    = (const float*)d_in[4];
    const float* noise_W  = (const float*)d_in[5];
    const float* noise_b  = (const float*)d_in[6];
    const float* mask_emb = (const float*)d_in[7];
    const float* pos_emb  = (const float*)d_in[8];
    const float* ln1_s    = (const float*)d_in[9];
    const float* ln1_b    = (const float*)d_in[10];
    const float* Wqkv     = (const float*)d_in[11];
    const float* bqkv     = (const float*)d_in[12];
    const float* Wo       = (const float*)d_in[13];
    const float* bo       = (const float*)d_in[14];
    const float* ln2_s    = (const float*)d_in[15];
    const float* ln2_b    = (const float*)d_in[16];
    const float* W1       = (const float*)d_in[17];
    const float* b1       = (const float*)d_in[18];
    const float* W2       = (const float*)d_in[19];
    const float* b2       = (const float*)d_in[20];
    // d_in[21] = members (constant E=2, compiled in)

    float *xp, *hp, *qkvp, *mlpp, *sp;
    cudaGetSymbolAddress((void**)&xp,   g_x);
    cudaGetSymbolAddress((void**)&hp,   g_h);
    cudaGetSymbolAddress((void**)&qkvp, g_qkv);
    cudaGetSymbolAddress((void**)&mlpp, g_mlp);
    cudaGetSymbolAddress((void**)&sp,   g_s);

    probe_visible<<<1, 32>>>(visible);
    embed_kernel<<<ROWS, 256>>>(fields, visible, W_in, mask_emb, pos_emb, noise_b, xp);

    // x += z @ noise_W  (noise_b already added in embed)
    sgemm128<<<dim3(DIM/128, ROWS/128), 256>>>(z, DIM, noise_W, DIM, xp, DIM,
                                               DIM, nullptr, 2);

    for (int l = 0; l < LAYERS; l++) {
        ln_kernel<<<ROWS, 256>>>(xp, ln1_s + l*DIM, ln1_b + l*DIM, hp);

        sgemm128<<<dim3(QKVD/128, ROWS/128), 256>>>(hp, DIM,
                                                    Wqkv + (size_t)l*DIM*QKVD, QKVD,
                                                    qkvp, QKVD,
                                                    DIM, bqkv + (size_t)l*QKVD, 0);

        attn_qk<<<dim3(8, 8, BE*NHEADS), 256>>>(qkvp, sp);
        softmax512<<<BE*NHEADS*NTOK, 256>>>(sp);
        attn_pv<<<dim3(8, BE*NHEADS), 256>>>(sp, qkvp, hp);

        sgemm128<<<dim3(DIM/128, ROWS/128), 256>>>(hp, DIM,
                                                   Wo + (size_t)l*DIM*DIM, DIM,
                                                   xp, DIM,
                                                   DIM, bo + (size_t)l*DIM, 2);

        ln_kernel<<<ROWS, 256>>>(xp, ln2_s + l*DIM, ln2_b + l*DIM, hp);

        sgemm128<<<dim3(DMLP/128, ROWS/128), 256>>>(hp, DIM,
                                                    W1 + (size_t)l*DIM*DMLP, DMLP,
                                                    mlpp, DMLP,
                                                    DIM, b1 + (size_t)l*DMLP, 1);

        sgemm128<<<dim3(DIM/128, ROWS/128), 256>>>(mlpp, DMLP,
                                                   W2 + (size_t)l*DMLP*DIM, DIM,
                                                   xp, DIM,
                                                   DMLP, b2 + (size_t)l*DIM, 2);
    }

    out_kernel<<<(BATCH*VIEWS*64*128*EMEM)/256, 256>>>(xp, W_out, (float*)d_out);
}

// round 2
// speedup vs baseline: 2.5967x; 2.5967x over previous
#include <cuda_runtime.h>
#include <cuda_bf16.h>
#include <cstddef>

// ---------------- problem constants ----------------
#define BATCH   8
#define EMEM    2
#define BE      16          // BATCH*EMEM
#define NTOK    512
#define ROWS    (BE*NTOK)   // 8192
#define DIM     768
#define NHEADS  12
#define HDIM    64
#define LAYERS  8
#define DMLP    3072
#define QKVD    2304
#define VIEWS   2

// ---------------- scratch (static device globals; no allocation) ----------------
__device__ float g_x[ROWS*DIM];          // residual stream
__device__ float g_h[ROWS*DIM];          // LN output / attention output
__device__ float g_qkv[ROWS*QKVD];       // qkv activations
__device__ float g_mlp[ROWS*DMLP];       // mlp hidden
__device__ float g_s[(size_t)BE*NHEADS*NTOK*NTOK]; // attention scores (201 MB)
__device__ int   g_vismode;              // 0=uint8, 1=int32, 2=float32

// ---------------- helpers ----------------
__device__ __forceinline__ float gelu_f(float x) {
    float x3 = x*x*x;
    return 0.5f*x*(1.f + tanhf(0.79788456080286535588f*(x + 0.044715f*x3)));
}

__device__ __forceinline__ unsigned f2tf32(float x) {
    unsigned r;
    asm("cvt.rna.tf32.f32 %0, %1;" : "=r"(r) : "f"(x));
    return r;
}

__device__ __forceinline__ void mma_tf32(float& c0, float& c1, float& c2, float& c3,
                                         unsigned a0, unsigned a1, unsigned a2, unsigned a3,
                                         unsigned b0, unsigned b1)
{
    asm volatile(
        "mma.sync.aligned.m16n8k8.row.col.f32.tf32.tf32.f32 "
        "{%0,%1,%2,%3},{%4,%5,%6,%7},{%8,%9},{%0,%1,%2,%3};"
        : "+f"(c0), "+f"(c1), "+f"(c2), "+f"(c3)
        : "r"(a0), "r"(a1), "r"(a2), "r"(a3), "r"(b0), "r"(b1));
}

// ---------------- probe dtype of `visible` ----------------
__global__ void probe_visible(const unsigned char* __restrict__ vis) {
    if (threadIdx.x == 0 && blockIdx.x == 0) {
        int nz1 = 0, nz3f = 0;
        for (int i = 0; i < 4096; i++) {
            int m = i & 3;
            if (m == 1 && vis[i]) nz1++;
            if (m == 3 && vis[i]) nz3f++;
        }
        if (nz1 != 0)       g_vismode = 0;
        else if (nz3f != 0) g_vismode = 2;
        else                g_vismode = 1;
    }
}

// ---------------- patch embed + mask + pos + noise bias ----------------
__global__ void embed_kernel(const float* __restrict__ fields,
                             const unsigned char* __restrict__ visible,
                             const float* __restrict__ W_in,
                             const float* __restrict__ mask_emb,
                             const float* __restrict__ pos_emb,
                             const float* __restrict__ noise_b,
                             float* __restrict__ xout)
{
    int row = blockIdx.x;            // 0..8191 : be*512 + n
    int be  = row >> 9;
    int n   = row & 511;
    int b   = be >> 1;
    int h   = n >> 5;
    int w   = n & 31;

    int vi = b*NTOK + n;
    bool vis;
    int mode = g_vismode;
    if (mode == 1)      vis = ((const int*)visible)[vi] != 0;
    else if (mode == 2) vis = ((const float*)visible)[vi] != 0.f;
    else                vis = visible[vi] != 0;

    __shared__ float fv[32];
    if (threadIdx.x < 32) {
        int v = threadIdx.x >> 4;
        int p = (threadIdx.x >> 2) & 3;
        int q = threadIdx.x & 3;
        fv[threadIdx.x] = fields[((size_t)(b*VIEWS + v)*64 + (h*4+p))*128 + (w*4+q)];
    }
    __syncthreads();

    for (int d = threadIdx.x; d < DIM; d += blockDim.x) {
        float acc;
        if (vis) {
            acc = 0.f;
            #pragma unroll
            for (int t = 0; t < 32; t++) acc += fv[t] * W_in[t*DIM + d];
        } else {
            acc = mask_emb[d];
        }
        xout[(size_t)row*DIM + d] = acc + pos_emb[n*DIM + d] + noise_b[d];
    }
}

// ---------------- tf32 tensor-core GEMM: 128x128 block, k-tile 16 ----------------
// C[M,N] = A[M,K] @ B[K,N] (+bias) (gelu) (+=C)
// flags: bit0 = gelu, bit1 = accumulate into C
// Requires: M%128==0, N%128==0, K%16==0, lda/ldb%4==0, 16B-aligned bases.
__global__ void __launch_bounds__(256) sgemm_tc(
    const float* __restrict__ A, int lda,
    const float* __restrict__ B, int ldb,
    float* __restrict__ C, int ldc,
    int K, const float* __restrict__ bias, int flags)
{
    __shared__ __align__(16) unsigned As[128][20];   // row stride 20 (=20 mod 32 -> 4*gid pattern)
    __shared__ __align__(16) unsigned Bs[16][136];   // row stride 136 (=8 mod 32)

    const int tid  = threadIdx.x;
    const int lane = tid & 31;
    const int wid  = tid >> 5;
    const int warpM = (wid >> 2) * 64;   // 2 warp-rows
    const int warpN = (wid & 3) * 32;    // 4 warp-cols
    const int gid = lane >> 2, tig = lane & 3;
    const int row0 = blockIdx.y * 128, col0 = blockIdx.x * 128;

    float acc[4][4][4];
    #pragma unroll
    for (int i = 0; i < 4; i++)
        #pragma unroll
        for (int j = 0; j < 4; j++)
            #pragma unroll
            for (int r = 0; r < 4; r++) acc[i][j][r] = 0.f;

    for (int k0 = 0; k0 < K; k0 += 16) {
        // stage A (128x16) as tf32
        #pragma unroll
        for (int i = 0; i < 2; i++) {
            int idx = tid + i*256;
            int r = idx >> 2, kq = idx & 3;
            float4 v = *(const float4*)&A[(size_t)(row0+r)*lda + k0 + kq*4];
            uint4 u = { f2tf32(v.x), f2tf32(v.y), f2tf32(v.z), f2tf32(v.w) };
            *(uint4*)&As[r][kq*4] = u;
        }
        // stage B (16x128) as tf32
        #pragma unroll
        for (int i = 0; i < 2; i++) {
            int idx = tid + i*256;
            int r = idx >> 5, nq = idx & 31;
            float4 v = *(const float4*)&B[(size_t)(k0+r)*ldb + col0 + nq*4];
            uint4 u = { f2tf32(v.x), f2tf32(v.y), f2tf32(v.z), f2tf32(v.w) };
            *(uint4*)&Bs[r][nq*4] = u;
        }
        __syncthreads();

        #pragma unroll
        for (int kk = 0; kk < 16; kk += 8) {
            unsigned a[4][4], b[4][2];
            #pragma unroll
            for (int mi = 0; mi < 4; mi++) {
                int rb = warpM + mi*16 + gid;
                a[mi][0] = As[rb    ][kk     + tig];
                a[mi][1] = As[rb + 8][kk     + tig];
                a[mi][2] = As[rb    ][kk + 4 + tig];
                a[mi][3] = As[rb + 8][kk + 4 + tig];
            }
            #pragma unroll
            for (int ni = 0; ni < 4; ni++) {
                int cb = warpN + ni*8 + gid;
                b[ni][0] = Bs[kk     + tig][cb];
                b[ni][1] = Bs[kk + 4 + tig][cb];
            }
            #pragma unroll
            for (int mi = 0; mi < 4; mi++)
                #pragma unroll
                for (int ni = 0; ni < 4; ni++)
                    mma_tf32(acc[mi][ni][0], acc[mi][ni][1], acc[mi][ni][2], acc[mi][ni][3],
                             a[mi][0], a[mi][1], a[mi][2], a[mi][3],
                             b[ni][0], b[ni][1]);
        }
        __syncthreads();
    }

    // epilogue
    #pragma unroll
    for (int mi = 0; mi < 4; mi++) {
        #pragma unroll
        for (int ni = 0; ni < 4; ni++) {
            int col = col0 + warpN + ni*8 + tig*2;
            float bia0 = bias ? bias[col]   : 0.f;
            float bia1 = bias ? bias[col+1] : 0.f;
            #pragma unroll
            for (int half = 0; half < 2; half++) {
                int row = row0 + warpM + mi*16 + gid + half*8;
                float v0 = acc[mi][ni][half*2 + 0] + bia0;
                float v1 = acc[mi][ni][half*2 + 1] + bia1;
                if (flags & 1) { v0 = gelu_f(v0); v1 = gelu_f(v1); }
                size_t ci = (size_t)row*ldc + col;
                if (flags & 2) { v0 += C[ci]; v1 += C[ci+1]; }
                C[ci]   = v0;
                C[ci+1] = v1;
            }
        }
    }
}

// ---------------- attention: S = scale * Q K^T (tf32 MMA) ----------------
__global__ void __launch_bounds__(256) attn_qk_tc(const float* __restrict__ qkv,
                                                  float* __restrict__ S)
{
    int bh = blockIdx.z;
    int be = bh / NHEADS, nh = bh % NHEADS;
    const float* Q  = qkv + (size_t)be*NTOK*QKVD + nh*HDIM;
    const float* Kp = Q + DIM;

    __shared__ __align__(16) unsigned Qs[64][68];  // 68 mod 32 = 4 -> conflict-free frag loads
    __shared__ __align__(16) unsigned Ks[64][68];

    const int tid = threadIdx.x;
    const int lane = tid & 31, wid = tid >> 5;
    const int gid = lane >> 2, tig = lane & 3;
    const int warpM = (wid >> 2) * 32;   // 2 warp-rows of 32
    const int warpN = (wid & 3) * 16;    // 4 warp-cols of 16
    const int qt = blockIdx.y * 64, kt = blockIdx.x * 64;

    // stage Q and K tiles (64 rows x 64 k), tf32
    #pragma unroll
    for (int i = 0; i < 4; i++) {
        int idx = tid + i*256;
        int r = idx >> 4, kq = idx & 15;
        float4 vq = *(const float4*)&Q [(size_t)(qt+r)*QKVD + kq*4];
        float4 vk = *(const float4*)&Kp[(size_t)(kt+r)*QKVD + kq*4];
        uint4 uq = { f2tf32(vq.x), f2tf32(vq.y), f2tf32(vq.z), f2tf32(vq.w) };
        uint4 uk = { f2tf32(vk.x), f2tf32(vk.y), f2tf32(vk.z), f2tf32(vk.w) };
        *(uint4*)&Qs[r][kq*4] = uq;
        *(uint4*)&Ks[r][kq*4] = uk;
    }
    __syncthreads();

    float acc[2][2][4];
    #pragma unroll
    for (int i = 0; i < 2; i++)
        #pragma unroll
        for (int j = 0; j < 2; j++)
            #pragma unroll
            for (int r = 0; r < 4; r++) acc[i][j][r] = 0.f;

    #pragma unroll
    for (int kk = 0; kk < 64; kk += 8) {
        unsigned a[2][4], b[2][2];
        #pragma unroll
        for (int mi = 0; mi < 2; mi++) {
            int rb = warpM + mi*16 + gid;
            a[mi][0] = Qs[rb    ][kk     + tig];
            a[mi][1] = Qs[rb + 8][kk     + tig];
            a[mi][2] = Qs[rb    ][kk + 4 + tig];
            a[mi][3] = Qs[rb + 8][kk + 4 + tig];
        }
        #pragma unroll
        for (int ni = 0; ni < 2; ni++) {
            int cb = warpN + ni*8 + gid;
            b[ni][0] = Ks[cb][kk     + tig];
            b[ni][1] = Ks[cb][kk + 4 + tig];
        }
        #pragma unroll
        for (int mi = 0; mi < 2; mi++)
            #pragma unroll
            for (int ni = 0; ni < 2; ni++)
                mma_tf32(acc[mi][ni][0], acc[mi][ni][1], acc[mi][ni][2], acc[mi][ni][3],
                         a[mi][0], a[mi][1], a[mi][2], a[mi][3],
                         b[ni][0], b[ni][1]);
    }

    float* Sb = S + (size_t)bh*NTOK*NTOK;
    const float scale = 0.125f;
    #pragma unroll
    for (int mi = 0; mi < 2; mi++)
        #pragma unroll
        for (int ni = 0; ni < 2; ni++) {
            int col = kt + warpN + ni*8 + tig*2;
            #pragma unroll
            for (int half = 0; half < 2; half++) {
                int row = qt + warpM + mi*16 + gid + half*8;
                Sb[(size_t)row*NTOK + col]   = acc[mi][ni][half*2+0]*scale;
                Sb[(size_t)row*NTOK + col+1] = acc[mi][ni][half*2+1]*scale;
            }
        }
}

// ---------------- softmax over last dim (rows of 512) ----------------
__global__ void softmax512(float* __restrict__ S)
{
    size_t row = blockIdx.x;
    float* p = S + row*512;
    int tid = threadIdx.x;
    float a = p[tid], b = p[tid+256];
    __shared__ float red[256];
    red[tid] = fmaxf(a, b);
    __syncthreads();
    for (int s = 128; s > 0; s >>= 1) {
        if (tid < s) red[tid] = fmaxf(red[tid], red[tid+s]);
        __syncthreads();
    }
    float m = red[0];
    __syncthreads();
    float e0 = __expf(a - m), e1 = __expf(b - m);
    red[tid] = e0 + e1;
    __syncthreads();
    for (int s = 128; s > 0; s >>= 1) {
        if (tid < s) red[tid] += red[tid+s];
        __syncthreads();
    }
    float inv = 1.f / red[0];
    p[tid]     = e0 * inv;
    p[tid+256] = e1 * inv;
}

// ---------------- attention: O = P @ V (tf32 MMA) ----------------
__global__ void __launch_bounds__(256) attn_pv_tc(const float* __restrict__ S,
                                                  const float* __restrict__ qkv,
                                                  float* __restrict__ H)
{
    int bh = blockIdx.y;
    int qt = blockIdx.x * 64;
    int be = bh / NHEADS, nh = bh % NHEADS;
    const float* P  = S + (size_t)bh*NTOK*NTOK;
    const float* Vv = qkv + (size_t)be*NTOK*QKVD + 2*DIM + nh*HDIM;

    __shared__ __align__(16) unsigned Ps[64][20];
    __shared__ __align__(16) unsigned Vs[16][72];   // 72 mod 32 = 8

    const int tid = threadIdx.x;
    const int lane = tid & 31, wid = tid >> 5;
    const int gid = lane >> 2, tig = lane & 3;
    const int warpM = (wid >> 2) * 32;
    const int warpN = (wid & 3) * 16;

    float acc[2][2][4];
    #pragma unroll
    for (int i = 0; i < 2; i++)
        #pragma unroll
        for (int j = 0; j < 2; j++)
            #pragma unroll
            for (int r = 0; r < 4; r++) acc[i][j][r] = 0.f;

    for (int k0 = 0; k0 < NTOK; k0 += 16) {
        {
            int r = tid >> 2, kq = tid & 3;   // 64x16 P tile: 256 float4
            float4 v = *(const float4*)&P[(size_t)(qt+r)*NTOK + k0 + kq*4];
            uint4 u = { f2tf32(v.x), f2tf32(v.y), f2tf32(v.z), f2tf32(v.w) };
            *(uint4*)&Ps[r][kq*4] = u;
        }
        {
            int r = tid >> 4, nq = tid & 15;  // 16x64 V tile: 256 float4
            float4 v = *(const float4*)&Vv[(size_t)(k0+r)*QKVD + nq*4];
            uint4 u = { f2tf32(v.x), f2tf32(v.y), f2tf32(v.z), f2tf32(v.w) };
            *(uint4*)&Vs[r][nq*4] = u;
        }
        __syncthreads();

        #pragma unroll
        for (int kk = 0; kk < 16; kk += 8) {
            unsigned a[2][4], b[2][2];
            #pragma unroll
            for (int mi = 0; mi < 2; mi++) {
                int rb = warpM + mi*16 + gid;
                a[mi][0] = Ps[rb    ][kk     + tig];
                a[mi][1] = Ps[rb + 8][kk     + tig];
                a[mi][2] = Ps[rb    ][kk + 4 + tig];
                a[mi][3] = Ps[rb + 8][kk + 4 + tig];
            }
            #pragma unroll
            for (int ni = 0; ni < 2; ni++) {
                int cb = warpN + ni*8 + gid;
                b[ni][0] = Vs[kk     + tig][cb];
                b[ni][1] = Vs[kk + 4 + tig][cb];
            }
            #pragma unroll
            for (int mi = 0; mi < 2; mi++)
                #pragma unroll
                for (int ni = 0; ni < 2; ni++)
                    mma_tf32(acc[mi][ni][0], acc[mi][ni][1], acc[mi][ni][2], acc[mi][ni][3],
                             a[mi][0], a[mi][1], a[mi][2], a[mi][3],
                             b[ni][0], b[ni][1]);
        }
        __syncthreads();
    }

    #pragma unroll
    for (int mi = 0; mi < 2; mi++)
        #pragma unroll
        for (int ni = 0; ni < 2; ni++) {
            int col = nh*HDIM + warpN + ni*8 + tig*2;
            #pragma unroll
            for (int half = 0; half < 2; half++) {
                int row = be*NTOK + qt + warpM + mi*16 + gid + half*8;
                H[(size_t)row*DIM + col]   = acc[mi][ni][half*2+0];
                H[(size_t)row*DIM + col+1] = acc[mi][ni][half*2+1];
            }
        }
}

// ---------------- layernorm (one block per row) ----------------
__global__ void ln_kernel(const float* __restrict__ x,
                          const float* __restrict__ s,
                          const float* __restrict__ b,
                          float* __restrict__ h)
{
    int row = blockIdx.x;
    const float* xr = x + (size_t)row*DIM;
    int tid = threadIdx.x;
    float v0 = xr[tid], v1 = xr[tid+256], v2 = xr[tid+512];
    __shared__ float red[256];
    red[tid] = v0 + v1 + v2;
    __syncthreads();
    for (int st = 128; st > 0; st >>= 1) {
        if (tid < st) red[tid] += red[tid+st];
        __syncthreads();
    }
    float mu = red[0] * (1.f/768.f);
    __syncthreads();
    float d0 = v0-mu, d1 = v1-mu, d2 = v2-mu;
    red[tid] = d0*d0 + d1*d1 + d2*d2;
    __syncthreads();
    for (int st = 128; st > 0; st >>= 1) {
        if (tid < st) red[tid] += red[tid+st];
        __syncthreads();
    }
    float rstd = rsqrtf(red[0]*(1.f/768.f) + 1e-5f);
    float* hr = h + (size_t)row*DIM;
    hr[tid]     = d0*rstd*s[tid]     + b[tid];
    hr[tid+256] = d1*rstd*s[tid+256] + b[tid+256];
    hr[tid+512] = d2*rstd*s[tid+512] + b[tid+512];
}

// ---------------- unpatchify + output transpose ----------------
__global__ void out_kernel(const float* __restrict__ x,
                           const float* __restrict__ W_out,
                           float* __restrict__ out)
{
    int idx = blockIdx.x*blockDim.x + threadIdx.x;   // 0..262143
    int e  = idx & 1;
    int Wc = (idx >> 1) & 127;
    int Hc = (idx >> 8) & 63;
    int v  = (idx >> 14) & 1;
    int b  = idx >> 15;
    int h = Hc >> 2, p = Hc & 3, w = Wc >> 2, q = Wc & 3;
    int row = (b*EMEM + e)*NTOK + h*32 + w;
    const float* xr = x + (size_t)row*DIM;
    const float* wr = W_out + ((size_t)v*DIM)*16 + p*4 + q;
    float acc = 0.f;
    #pragma unroll 4
    for (int d = 0; d < DIM; d++) acc += xr[d] * wr[(size_t)d*16];
    out[idx] = acc;
}

// ---------------- driver ----------------
extern "C" void kernel_launch(void* const* d_in, const int* in_sizes, int n_in,
                              void* d_out, int out_size)
{
    const float* fields   = (const float*)d_in[0];
    const unsigned char* visible = (const unsigned char*)d_in[1];
    const float* z        = (const float*)d_in[2];
    const float* W_in     = (const float*)d_in[3];
    const float* W_out    = (const float*)d_in[4];
    const float* noise_W  = (const float*)d_in[5];
    const float* noise_b  = (const float*)d_in[6];
    const float* mask_emb = (const float*)d_in[7];
    const float* pos_emb  = (const float*)d_in[8];
    const float* ln1_s    = (const float*)d_in[9];
    const float* ln1_b    = (const float*)d_in[10];
    const float* Wqkv     = (const float*)d_in[11];
    const float* bqkv     = (const float*)d_in[12];
    const float* Wo       = (const float*)d_in[13];
    const float* bo       = (const float*)d_in[14];
    const float* ln2_s    = (const float*)d_in[15];
    const float* ln2_b    = (const float*)d_in[16];
    const float* W1       = (const float*)d_in[17];
    const float* b1       = (const float*)d_in[18];
    const float* W2       = (const float*)d_in[19];
    const float* b2       = (const float*)d_in[20];

    float *xp, *hp, *qkvp, *mlpp, *sp;
    cudaGetSymbolAddress((void**)&xp,   g_x);
    cudaGetSymbolAddress((void**)&hp,   g_h);
    cudaGetSymbolAddress((void**)&qkvp, g_qkv);
    cudaGetSymbolAddress((void**)&mlpp, g_mlp);
    cudaGetSymbolAddress((void**)&sp,   g_s);

    probe_visible<<<1, 32>>>(visible);
    embed_kernel<<<ROWS, 256>>>(fields, visible, W_in, mask_emb, pos_emb, noise_b, xp);

    // x += z @ noise_W
    sgemm_tc<<<dim3(DIM/128, ROWS/128), 256>>>(z, DIM, noise_W, DIM, xp, DIM,
                                               DIM, nullptr, 2);

    for (int l = 0; l < LAYERS; l++) {
        ln_kernel<<<ROWS, 256>>>(xp, ln1_s + l*DIM, ln1_b + l*DIM, hp);

        sgemm_tc<<<dim3(QKVD/128, ROWS/128), 256>>>(hp, DIM,
                                                    Wqkv + (size_t)l*DIM*QKVD, QKVD,
                                                    qkvp, QKVD,
                                                    DIM, bqkv + (size_t)l*QKVD, 0);

        attn_qk_tc<<<dim3(8, 8, BE*NHEADS), 256>>>(qkvp, sp);
        softmax512<<<BE*NHEADS*NTOK, 256>>>(sp);
        attn_pv_tc<<<dim3(8, BE*NHEADS), 256>>>(sp, qkvp, hp);

        sgemm_tc<<<dim3(DIM/128, ROWS/128), 256>>>(hp, DIM,
                                                   Wo + (size_t)l*DIM*DIM, DIM,
                                                   xp, DIM,
                                                   DIM, bo + (size_t)l*DIM, 2);

        ln_kernel<<<ROWS, 256>>>(xp, ln2_s + l*DIM, ln2_b + l*DIM, hp);

        sgemm_tc<<<dim3(DMLP/128, ROWS/128), 256>>>(hp, DIM,
                                                    W1 + (size_t)l*DIM*DMLP, DMLP,
                                                    mlpp, DMLP,
                                                    DIM, b1 + (size_t)l*DMLP, 1);

        sgemm_tc<<<dim3(DIM/128, ROWS/128), 256>>>(mlpp, DMLP,
                                                   W2 + (size_t)l*DMLP*DIM, DIM,
                                                   xp, DIM,
                                                   DMLP, b2 + (size_t)l*DIM, 2);
    }

    out_kernel<<<(BATCH*VIEWS*64*128*EMEM)/256, 256>>>(xp, W_out, (float*)d_out);
}